// round 11
// baseline (speedup 1.0000x reference)
#include <cuda_runtime.h>
#include <cuda_fp16.h>

// Problem shape (fixed by the dataset): B=8, N=M=2048, 3-D points.
#define kB 8
#define kN 2048
#define kM 2048

// Fused A+C geometry: 256 threads = 8 warps, RPW=4 rows/warp -> 32 rows/CTA
#define RPW 4
#define ROWS_PER_CTA 32
#define GRID_AC (kB * kN / ROWS_PER_CTA)            // 512 (1 wave at 4 CTA/SM)

// Pass B+E geometry: thread-per-column tile of 256, n chunks of 256
#define MTILE 256
#define NCHUNK 256
#define NCHUNKS (kN / NCHUNK)                       // 8
#define NMT (kM / MTILE)                            // 8
#define GRID_B (kB * NMT * NCHUNKS)                 // 512

#define SKIP_X (-60.0f)
#define LOG2E 1.4426950408889634f
#define DEAD_LG (-1e30f)     // stands in for log2(0); ex2 underflows to exact 0

typedef unsigned long long ull;

// ---------------- scratch (static __device__, no allocation) ----------------
__device__ float4  g_P1[kB][kN];                // (x,y,z,|p|^2)
__device__ float4  g_P2[kB][kM];                // (x,y,z,|q|^2)
__device__ float   g_rowmin[kB][kN];
__device__ float   g_rowscale[kB][kN];
__device__ float4  g_rowB[kB][kN];              // (l2*-2x, l2*-2y, l2*-2z, l2*|p|^2 + lg2(rs))
__device__ float   g_remainL[kB][kN];
__device__ float   g_remainR[kB][kM];
__device__ float4  g_wpk[kB][kM / 2];           // (remReff0, remReff1, remainR0, remainR1) m-pairs
__device__ float   g_colsum[kB][NCHUNKS][kM];
__device__ float   g_colsumd[kB][NCHUNKS][kM];
__device__ float   g_costPart[kB][NMT];
__device__ float   g_sumRPart[kB][NMT];
__device__ unsigned int g_ticket[kB][NMT];      // last-CTA election for fused E
__device__ __half2 g_d16[kB][kN / 2][kM];       // 64 MB distance table, pair over n

// ---------------- helpers ----------------
__device__ __forceinline__ float ex2f(float x) {
    float r; asm("ex2.approx.f32 %0, %1;" : "=f"(r) : "f"(x)); return r;
}
__device__ __forceinline__ float lg2f(float x) {
    float r; asm("lg2.approx.f32 %0, %1;" : "=f"(r) : "f"(x)); return r;
}
__device__ __forceinline__ float sqrt_apx(float x) {
    float r; asm("sqrt.approx.f32 %0, %1;" : "=f"(r) : "f"(x)); return r;
}
__device__ __forceinline__ ull pk(float lo, float hi) {
    ull r; asm("mov.b64 %0, {%1, %2};" : "=l"(r) : "f"(lo), "f"(hi)); return r;
}
__device__ __forceinline__ float2 upk(ull v) {
    float lo, hi; asm("mov.b64 {%0, %1}, %2;" : "=f"(lo), "=f"(hi) : "l"(v));
    return make_float2(lo, hi);
}
__device__ __forceinline__ ull fma2(ull a, ull b, ull c) {
    ull r; asm("fma.rn.f32x2 %0, %1, %2, %3;" : "=l"(r) : "l"(a), "l"(b), "l"(c)); return r;
}
__device__ __forceinline__ ull add2(ull a, ull b) {
    ull r; asm("add.rn.f32x2 %0, %1, %2;" : "=l"(r) : "l"(a), "l"(b)); return r;
}
__device__ __forceinline__ ull mul2(ull a, ull b) {
    ull r; asm("mul.rn.f32x2 %0, %1, %2;" : "=l"(r) : "l"(a), "l"(b)); return r;
}
__device__ __forceinline__ float warp_sum(float v) {
    #pragma unroll
    for (int o = 16; o; o >>= 1) v += __shfl_xor_sync(0xffffffffu, v, o);
    return v;
}

// ---------------- init ----------------
__global__ void k_init(const float* __restrict__ in1, const float* __restrict__ in2) {
    int idx = blockIdx.x * blockDim.x + threadIdx.x;   // over kB*kN
    if (idx < kB * kN) {
        int b = idx / kN, n = idx % kN;
        const float* p1 = in1 + (size_t)idx * 3;
        const float* p2 = in2 + (size_t)idx * 3;
        float x1 = p1[0], y1 = p1[1], z1 = p1[2];
        float x2 = p2[0], y2 = p2[1], z2 = p2[2];
        g_P1[b][n] = make_float4(x1, y1, z1, x1 * x1 + y1 * y1 + z1 * z1);
        g_P2[b][n] = make_float4(x2, y2, z2, x2 * x2 + y2 * y2 + z2 * z2);
        g_remainL[b][n] = 1.0f;
        g_remainR[b][n] = 1.0f;
        g_rowscale[b][n] = 0.0f;
        if (n < kM / 2) g_wpk[b][n] = make_float4(0.0f, 0.0f, 1.0f, 1.0f);
    }
    if (idx < kB * NMT) {
        g_costPart[idx / NMT][idx % NMT] = 0.0f;
        g_ticket[idx / NMT][idx % NMT] = 0u;
    }
}

// ---------------- rowmin (one-time) ----------------
__global__ void __launch_bounds__(256) k_rowmin() {
    __shared__ float4 s2[kM];
    int cta = blockIdx.x;                                  // over kB * kN/32
    int b = cta / (kN / 32);
    int rowbase = (cta % (kN / 32)) * 32;
    for (int i = threadIdx.x; i < kM; i += 256) s2[i] = g_P2[b][i];
    __syncthreads();
    int warp = threadIdx.x >> 5, lane = threadIdx.x & 31;
    float4 p = g_P1[b][rowbase + lane];
    float mn = 3.4e38f;
    for (int m = warp * (kM / 8); m < (warp + 1) * (kM / 8); m++) {
        float4 q = s2[m];                                   // broadcast
        float dx = p.x - q.x, dy = p.y - q.y, dz = p.z - q.z;
        mn = fminf(mn, dx * dx + dy * dy + dz * dz);
    }
    __shared__ float smn[8][33];
    smn[warp][lane] = mn;
    __syncthreads();
    if (warp == 0) {
        float v = smn[0][lane];
        #pragma unroll
        for (int w = 1; w < 8; w++) v = fminf(v, smn[w][lane]);
        g_rowmin[b][rowbase + lane] = v;
    }
}

// ---------------- one-time distance table: d16[b][n/2][m] = fp16 sqrt(d2) ----------------
__global__ void __launch_bounds__(256) k_dprep() {
    __shared__ float4 s1[NCHUNK];
    int cta = blockIdx.x;
    int b = cta / (NMT * NCHUNKS);
    int rem = cta % (NMT * NCHUNKS);
    int mtile = rem / NCHUNKS;
    int chunk = rem % NCHUNKS;
    int nbase = chunk * NCHUNK;
    s1[threadIdx.x] = g_P1[b][nbase + threadIdx.x];
    __syncthreads();
    int m = mtile * MTILE + threadIdx.x;
    float4 q = g_P2[b][m];
    int jbase = nbase >> 1;
    #pragma unroll 4
    for (int j = 0; j < NCHUNK / 2; j++) {
        float4 p0 = s1[2 * j], p1 = s1[2 * j + 1];
        float dx0 = p0.x - q.x, dy0 = p0.y - q.y, dz0 = p0.z - q.z;
        float dx1 = p1.x - q.x, dy1 = p1.y - q.y, dz1 = p1.z - q.z;
        float d0 = sqrt_apx(dx0 * dx0 + dy0 * dy0 + dz0 * dz0);
        float d1 = sqrt_apx(dx1 * dx1 + dy1 * dy1 + dz1 * dz1);
        g_d16[b][jbase + j][m] = __floats2half2_rn(d0, d1);
    }
}

// ---------------- fused pass: C(level j-1) + A(level j), m-pair form, RPW=4 ----------------
// NORMAL (LAST=false): lvl_prev = 4*lvl_cur exactly -> e_prev = (e^2)^2, one ex2/elem.
// LAST   (LAST=true):  level j=9 (cur=0): A trivial (rowsum = sum remainR), C at lvl2p.
// Weights (remReff, remainR) come packed from global g_wpk (coalesced LDG.128).
template<bool LAST>
__global__ void __launch_bounds__(256, 4) k_fusedAC(float lvl2p, float lvl2c) {
    __shared__ float4 s_xy[kM / 2];   // (x0,x1,y0,y1)           16 KB
    __shared__ float4 s_zc[kM / 2];   // (z0,z1,lF*c0,lF*c1)     16 KB
    __shared__ float  s_sumR;
    int cta = blockIdx.x;
    int b = cta / (kN / ROWS_PER_CTA);
    int rowbase = (cta % (kN / ROWS_PER_CTA)) * ROWS_PER_CTA;
    int warp = threadIdx.x >> 5, lane = threadIdx.x & 31;
    float lvlF = LAST ? lvl2p : lvl2c;

    // per-warp row constants, duplicated-packed ONCE (lvl folded)
    ull bx2[RPW], by2[RPW], bz2[RPW], bc2[RPW];
    float rsPrev[RPW];
    bool liveA[RPW];
    bool anyA = false, anyC = false;
    #pragma unroll
    for (int r = 0; r < RPW; r++) {
        int n = rowbase + warp * RPW + r;
        float4 p = g_P1[b][n];
        float bx = lvlF * -2.0f * p.x, by = lvlF * -2.0f * p.y;
        float bz = lvlF * -2.0f * p.z, bc = lvlF * p.w;
        bx2[r] = pk(bx, bx); by2[r] = pk(by, by);
        bz2[r] = pk(bz, bz); bc2[r] = pk(bc, bc);
        rsPrev[r] = g_rowscale[b][n];
        liveA[r] = (!LAST) && (lvl2c * g_rowmin[b][n] >= SKIP_X);
        anyA |= liveA[r];
        anyC |= (rsPrev[r] != 0.0f);
    }
    if (LAST && threadIdx.x == 0) {
        float s = 0.0f;
        #pragma unroll
        for (int mt = 0; mt < NMT; mt++) s += g_sumRPart[b][mt];
        s_sumR = s;
    }
    int ctaAny = __syncthreads_or((anyA || anyC) ? 1 : 0);

    ull accA[RPW] = {0ull, 0ull, 0ull, 0ull};
    ull accC[RPW] = {0ull, 0ull, 0ull, 0ull};
    if (ctaAny) {
        for (int j = threadIdx.x; j < kM / 2; j += 256) {
            float4 qa = g_P2[b][2 * j], qb = g_P2[b][2 * j + 1];
            s_xy[j] = make_float4(qa.x, qb.x, qa.y, qb.y);
            s_zc[j] = make_float4(qa.z, qb.z, lvlF * qa.w, lvlF * qb.w);
        }
        __syncthreads();
        const ulonglong2* wp = reinterpret_cast<const ulonglong2*>(&g_wpk[b][0]);
        #pragma unroll 2
        for (int j = lane; j < kM / 2; j += 32) {
            ulonglong2 xy = *reinterpret_cast<const ulonglong2*>(&s_xy[j]);
            ulonglong2 zc = *reinterpret_cast<const ulonglong2*>(&s_zc[j]);
            ulonglong2 w  = wp[j];            // (rf pair, rr pair) from L2, coalesced
            #pragma unroll
            for (int r = 0; r < RPW; r++) {
                ull a = add2(bc2[r], zc.y);
                a = fma2(bx2[r], xy.x, a);
                a = fma2(by2[r], xy.y, a);
                a = fma2(bz2[r], zc.x, a);
                float2 af = upk(a);
                ull e = pk(ex2f(af.x), ex2f(af.y));
                if (!LAST) {
                    ull e2 = mul2(e, e);
                    ull e4 = mul2(e2, e2);
                    accC[r] = fma2(e4, w.x, accC[r]);
                    accA[r] = fma2(e, w.y, accA[r]);
                } else {
                    accC[r] = fma2(e, w.x, accC[r]);
                }
            }
        }
    }

    #pragma unroll
    for (int r = 0; r < RPW; r++) {
        float2 c2 = upk(accC[r]);
        float2 a2 = upk(accA[r]);
        float sC = warp_sum(c2.x + c2.y);
        float sA = warp_sum(a2.x + a2.y);
        if (lane == 0) {
            int n = rowbase + warp * RPW + r;
            float remL = g_remainL[b][n];
            remL = fmaxf(remL - rsPrev[r] * sC, 0.0f);
            g_remainL[b][n] = remL;
            float rs;
            if (LAST)            rs = remL / (s_sumR + 1e-9f);
            else if (liveA[r])   rs = remL / (sA + 1e-9f);
            else                 rs = 0.0f;
            g_rowscale[b][n] = rs;
            float lg = (rs > 0.0f) ? lg2f(rs) : DEAD_LG;
            float l2 = LAST ? 0.0f : lvl2c;
            float4 p = g_P1[b][n];
            g_rowB[b][n] = make_float4(l2 * -2.0f * p.x, l2 * -2.0f * p.y,
                                       l2 * -2.0f * p.z, fmaf(l2, p.w, lg));
        }
    }
}

// ---------------- fused pass B + E ----------------
// Column partials with rowscale folded as lg2, d from fp16 table; the last CTA per
// (b, mtile) group (ticket election, deterministic fixed-order sums) runs the E
// phase: clip, cost, remainR update, packed weight write for next AC.
__global__ void __launch_bounds__(256) k_passBE(float lvl2) {
    __shared__ float4 sXY[NCHUNK / 2];   // (x0,x1,y0,y1) of rowB, row-pair packed
    __shared__ float4 sZC[NCHUNK / 2];   // (z0,z1,c0,c1)
    __shared__ float  r1[256], r2[256];
    __shared__ float  sRf[256], sNr[256];
    __shared__ unsigned int s_arr;
    int cta = blockIdx.x;
    int b = cta / (NMT * NCHUNKS);
    int rem = cta % (NMT * NCHUNKS);
    int mtile = rem / NCHUNKS;
    int chunk = rem % NCHUNKS;
    int nbase = chunk * NCHUNK;

    bool liveT = false;
    if (threadIdx.x < NCHUNK / 2) {
        float4 r0 = g_rowB[b][nbase + 2 * threadIdx.x];
        float4 rr = g_rowB[b][nbase + 2 * threadIdx.x + 1];
        sXY[threadIdx.x] = make_float4(r0.x, rr.x, r0.y, rr.y);
        sZC[threadIdx.x] = make_float4(r0.z, rr.z, r0.w, rr.w);
        liveT = (r0.w > -1e29f) || (rr.w > -1e29f);
    }
    int any = __syncthreads_or(liveT ? 1 : 0);
    int m = mtile * MTILE + threadIdx.x;

    if (any) {
        float4 q = g_P2[b][m];
        float qc = lvl2 * q.w;
        ull qxx = pk(q.x, q.x), qyy = pk(q.y, q.y), qzz = pk(q.z, q.z), qcc = pk(qc, qc);
        const __half2* dp = &g_d16[b][nbase >> 1][m];
        ull csA = 0ull, cdA = 0ull, csB = 0ull, cdB = 0ull;   // dual chains (even/odd j)
        #pragma unroll 4
        for (int j = 0; j < NCHUNK / 2; j += 2) {
            {
                ulonglong2 xy = *reinterpret_cast<const ulonglong2*>(&sXY[j]);
                ulonglong2 zc = *reinterpret_cast<const ulonglong2*>(&sZC[j]);
                ull a = add2(zc.y, qcc);
                a = fma2(xy.x, qxx, a);
                a = fma2(xy.y, qyy, a);
                a = fma2(zc.x, qzz, a);
                float2 af = upk(a);
                ull e = pk(ex2f(af.x), ex2f(af.y));
                csA = add2(csA, e);
                float2 df = __half22float2(dp[j * kM]);
                cdA = fma2(e, pk(df.x, df.y), cdA);
            }
            {
                ulonglong2 xy = *reinterpret_cast<const ulonglong2*>(&sXY[j + 1]);
                ulonglong2 zc = *reinterpret_cast<const ulonglong2*>(&sZC[j + 1]);
                ull a = add2(zc.y, qcc);
                a = fma2(xy.x, qxx, a);
                a = fma2(xy.y, qyy, a);
                a = fma2(zc.x, qzz, a);
                float2 af = upk(a);
                ull e = pk(ex2f(af.x), ex2f(af.y));
                csB = add2(csB, e);
                float2 df = __half22float2(dp[(j + 1) * kM]);
                cdB = fma2(e, pk(df.x, df.y), cdB);
            }
        }
        float2 ca = upk(csA), cb = upk(csB), da = upk(cdA), db = upk(cdB);
        float remR = g_remainR[b][m];
        g_colsum[b][chunk][m]  = ((ca.x + ca.y) + (cb.x + cb.y)) * remR;
        g_colsumd[b][chunk][m] = ((da.x + da.y) + (db.x + db.y)) * remR;
    } else {
        g_colsum[b][chunk][m]  = 0.0f;
        g_colsumd[b][chunk][m] = 0.0f;
    }

    // -- arrive: elect the last CTA of this (b, mtile) group to run the E phase --
    __threadfence();
    __syncthreads();
    if (threadIdx.x == 0) s_arr = atomicAdd(&g_ticket[b][mtile], 1u);
    __syncthreads();
    if (s_arr != NCHUNKS - 1) return;
    __threadfence();                               // see all groups' partial writes

    float cs = 0.0f, csd = 0.0f;
    #pragma unroll
    for (int c = 0; c < NCHUNKS; c++) { cs += g_colsum[b][c][m]; csd += g_colsumd[b][c][m]; }
    float rr = g_remainR[b][m];
    float csc = fminf(rr / (cs + 1e-9f), 1.0f);
    float rf = rr * csc;
    float nr = fmaxf(rr - cs * csc, 0.0f);
    g_remainR[b][m] = nr;
    sRf[threadIdx.x] = rf;
    sNr[threadIdx.x] = nr;
    r1[threadIdx.x] = csd * csc;
    r2[threadIdx.x] = nr;
    __syncthreads();
    if (threadIdx.x < MTILE / 2) {                 // packed weights for next AC launch
        int t = threadIdx.x;
        g_wpk[b][mtile * (MTILE / 2) + t] =
            make_float4(sRf[2 * t], sRf[2 * t + 1], sNr[2 * t], sNr[2 * t + 1]);
    }
    #pragma unroll
    for (int s = 128; s > 0; s >>= 1) {
        if (threadIdx.x < s) {
            r1[threadIdx.x] += r1[threadIdx.x + s];
            r2[threadIdx.x] += r2[threadIdx.x + s];
        }
        __syncthreads();
    }
    if (threadIdx.x == 0) {
        g_costPart[b][mtile] += r1[0];
        g_sumRPart[b][mtile] = r2[0];
        g_ticket[b][mtile] = 0u;                   // re-arm for next level / next replay
    }
}

// ---------------- final: reduce cost partials into out ----------------
__global__ void k_final(float* __restrict__ out) {
    int b = blockIdx.x;
    int lane = threadIdx.x;
    float v = (lane < NMT) ? g_costPart[b][lane] : 0.0f;
    v = warp_sum(v);
    if (lane == 0) out[b] = v;
}

// ---------------- launch ----------------
extern "C" void kernel_launch(void* const* d_in, const int* in_sizes, int n_in,
                              void* d_out, int out_size) {
    const float* in1 = (const float*)d_in[0];
    const float* in2 = (const float*)d_in[1];
    float* out = (float*)d_out;

    static const float levels[10] = {
        -16384.f, -4096.f, -1024.f, -256.f, -64.f, -16.f, -4.f, -1.f, -0.25f, 0.f
    };

    k_init<<<(kB * kN + 255) / 256, 256>>>(in1, in2);
    k_rowmin<<<kB * (kN / 32), 256>>>();
    k_dprep<<<GRID_B, 256>>>();
    float lp = 0.0f;
    for (int j = 0; j < 10; j++) {
        float lc = levels[j] * LOG2E;
        if (j < 9) k_fusedAC<false><<<GRID_AC, 256>>>(lp, lc);
        else       k_fusedAC<true ><<<GRID_AC, 256>>>(lp, lc);
        k_passBE<<<GRID_B, 256>>>(lc);
        lp = lc;
    }
    k_final<<<kB, 32>>>(out);
}

// round 13
// speedup vs baseline: 1.0457x; 1.0457x over previous
#include <cuda_runtime.h>
#include <cuda_fp16.h>

// Problem shape (fixed by the dataset): B=8, N=M=2048, 3-D points.
#define kB 8
#define kN 2048
#define kM 2048

// Fused A+C geometry: 256 threads = 8 warps, RPW=2 rows/warp -> 16 rows/CTA
#define RPW 2
#define ROWS_PER_CTA 16
#define GRID_AC (kB * kN / ROWS_PER_CTA)            // 1024

// Pass B+E geometry: thread-per-column tile of 256, n chunks of 256
#define MTILE 256
#define NCHUNK 256
#define NCHUNKS (kN / NCHUNK)                       // 8
#define NMT (kM / MTILE)                            // 8
#define GRID_B (kB * NMT * NCHUNKS)                 // 512

#define SKIP_X (-60.0f)
#define LOG2E 1.4426950408889634f
#define DEAD_LG (-1e30f)     // stands in for log2(0); ex2 underflows to exact 0

typedef unsigned long long ull;

// ---------------- scratch (static __device__, no allocation) ----------------
__device__ float4  g_P1[kB][kN];                // (x,y,z,|p|^2)
__device__ float4  g_P2[kB][kM];                // (x,y,z,|q|^2)
__device__ float   g_rowmin[kB][kN];
__device__ float   g_rowscale[kB][kN];
__device__ float4  g_rowB[kB][kN];              // (l2*-2x, l2*-2y, l2*-2z, l2*|p|^2 + lg2(rs))
__device__ float   g_remainL[kB][kN];
__device__ float   g_remainR[kB][kM];
__device__ float4  g_wpk[kB][kM / 2];           // (remReff0, remReff1, remainR0, remainR1) m-pairs
__device__ float   g_colsum[kB][NCHUNKS][kM];
__device__ float   g_colsumd[kB][NCHUNKS][kM];
__device__ float   g_costPart[kB][NMT];
__device__ float   g_sumRPart[kB][NMT];
__device__ unsigned int g_ticket[kB][NMT];      // last-CTA election for fused E
__device__ __half2 g_d16[kB][kN / 2][kM];       // 64 MB distance table, pair over n

// ---------------- helpers ----------------
__device__ __forceinline__ float ex2f(float x) {
    float r; asm("ex2.approx.f32 %0, %1;" : "=f"(r) : "f"(x)); return r;
}
__device__ __forceinline__ float lg2f(float x) {
    float r; asm("lg2.approx.f32 %0, %1;" : "=f"(r) : "f"(x)); return r;
}
__device__ __forceinline__ float sqrt_apx(float x) {
    float r; asm("sqrt.approx.f32 %0, %1;" : "=f"(r) : "f"(x)); return r;
}
__device__ __forceinline__ ull pk(float lo, float hi) {
    ull r; asm("mov.b64 %0, {%1, %2};" : "=l"(r) : "f"(lo), "f"(hi)); return r;
}
__device__ __forceinline__ float2 upk(ull v) {
    float lo, hi; asm("mov.b64 {%0, %1}, %2;" : "=f"(lo), "=f"(hi) : "l"(v));
    return make_float2(lo, hi);
}
__device__ __forceinline__ ull fma2(ull a, ull b, ull c) {
    ull r; asm("fma.rn.f32x2 %0, %1, %2, %3;" : "=l"(r) : "l"(a), "l"(b), "l"(c)); return r;
}
__device__ __forceinline__ ull add2(ull a, ull b) {
    ull r; asm("add.rn.f32x2 %0, %1, %2;" : "=l"(r) : "l"(a), "l"(b)); return r;
}
__device__ __forceinline__ ull mul2(ull a, ull b) {
    ull r; asm("mul.rn.f32x2 %0, %1, %2;" : "=l"(r) : "l"(a), "l"(b)); return r;
}
__device__ __forceinline__ float warp_sum(float v) {
    #pragma unroll
    for (int o = 16; o; o >>= 1) v += __shfl_xor_sync(0xffffffffu, v, o);
    return v;
}

// ---------------- init ----------------
__global__ void k_init(const float* __restrict__ in1, const float* __restrict__ in2) {
    int idx = blockIdx.x * blockDim.x + threadIdx.x;   // over kB*kN
    if (idx < kB * kN) {
        int b = idx / kN, n = idx % kN;
        const float* p1 = in1 + (size_t)idx * 3;
        const float* p2 = in2 + (size_t)idx * 3;
        float x1 = p1[0], y1 = p1[1], z1 = p1[2];
        float x2 = p2[0], y2 = p2[1], z2 = p2[2];
        g_P1[b][n] = make_float4(x1, y1, z1, x1 * x1 + y1 * y1 + z1 * z1);
        g_P2[b][n] = make_float4(x2, y2, z2, x2 * x2 + y2 * y2 + z2 * z2);
        g_remainL[b][n] = 1.0f;
        g_remainR[b][n] = 1.0f;
        g_rowscale[b][n] = 0.0f;
        if (n < kM / 2) g_wpk[b][n] = make_float4(0.0f, 0.0f, 1.0f, 1.0f);
    }
    if (idx < kB * NMT) {
        g_costPart[idx / NMT][idx % NMT] = 0.0f;
        g_ticket[idx / NMT][idx % NMT] = 0u;
    }
}

// ---------------- rowmin (one-time) ----------------
__global__ void __launch_bounds__(256) k_rowmin() {
    __shared__ float4 s2[kM];
    int cta = blockIdx.x;                                  // over kB * kN/32
    int b = cta / (kN / 32);
    int rowbase = (cta % (kN / 32)) * 32;
    for (int i = threadIdx.x; i < kM; i += 256) s2[i] = g_P2[b][i];
    __syncthreads();
    int warp = threadIdx.x >> 5, lane = threadIdx.x & 31;
    float4 p = g_P1[b][rowbase + lane];
    float mn = 3.4e38f;
    for (int m = warp * (kM / 8); m < (warp + 1) * (kM / 8); m++) {
        float4 q = s2[m];                                   // broadcast
        float dx = p.x - q.x, dy = p.y - q.y, dz = p.z - q.z;
        mn = fminf(mn, dx * dx + dy * dy + dz * dz);
    }
    __shared__ float smn[8][33];
    smn[warp][lane] = mn;
    __syncthreads();
    if (warp == 0) {
        float v = smn[0][lane];
        #pragma unroll
        for (int w = 1; w < 8; w++) v = fminf(v, smn[w][lane]);
        g_rowmin[b][rowbase + lane] = v;
    }
}

// ---------------- one-time distance table: d16[b][n/2][m] = fp16 sqrt(d2) ----------------
__global__ void __launch_bounds__(256) k_dprep() {
    __shared__ float4 s1[NCHUNK];
    int cta = blockIdx.x;
    int b = cta / (NMT * NCHUNKS);
    int rem = cta % (NMT * NCHUNKS);
    int mtile = rem / NCHUNKS;
    int chunk = rem % NCHUNKS;
    int nbase = chunk * NCHUNK;
    s1[threadIdx.x] = g_P1[b][nbase + threadIdx.x];
    __syncthreads();
    int m = mtile * MTILE + threadIdx.x;
    float4 q = g_P2[b][m];
    int jbase = nbase >> 1;
    #pragma unroll 4
    for (int j = 0; j < NCHUNK / 2; j++) {
        float4 p0 = s1[2 * j], p1 = s1[2 * j + 1];
        float dx0 = p0.x - q.x, dy0 = p0.y - q.y, dz0 = p0.z - q.z;
        float dx1 = p1.x - q.x, dy1 = p1.y - q.y, dz1 = p1.z - q.z;
        float d0 = sqrt_apx(dx0 * dx0 + dy0 * dy0 + dz0 * dz0);
        float d1 = sqrt_apx(dx1 * dx1 + dy1 * dy1 + dz1 * dz1);
        g_d16[b][jbase + j][m] = __floats2half2_rn(d0, d1);
    }
}

// ---------------- fused pass: C(level j-1) + A(level j), m-pair form, RPW=2 ----------------
// (R8 configuration — measured 16.4us dense.) NORMAL: lvl_prev = 4*lvl_cur exactly
// -> e_prev = (e^2)^2, one ex2/elem. LAST (j=9): A trivial, C at lvl2p.
// Weights staged in smem s_w, filled from packed g_wpk (vector loads, fill-loop only).
template<bool LAST>
__global__ void __launch_bounds__(256) k_fusedAC(float lvl2p, float lvl2c) {
    __shared__ float4 s_xy[kM / 2];   // (x0,x1,y0,y1)           16 KB
    __shared__ float4 s_zc[kM / 2];   // (z0,z1,lF*c0,lF*c1)     16 KB
    __shared__ float4 s_w [kM / 2];   // (rf0,rf1,rr0,rr1)       16 KB
    __shared__ float  s_sumR;
    int cta = blockIdx.x;
    int b = cta / (kN / ROWS_PER_CTA);
    int rowbase = (cta % (kN / ROWS_PER_CTA)) * ROWS_PER_CTA;
    int warp = threadIdx.x >> 5, lane = threadIdx.x & 31;
    float lvlF = LAST ? lvl2p : lvl2c;

    // per-warp row constants, duplicated-packed ONCE
    ull bx2[RPW], by2[RPW], bz2[RPW], bc2[RPW];
    float rsPrev[RPW];
    bool liveA[RPW];
    bool anyA = false, anyC = false;
    #pragma unroll
    for (int r = 0; r < RPW; r++) {
        int n = rowbase + warp * RPW + r;
        float4 p = g_P1[b][n];
        float bx = lvlF * -2.0f * p.x, by = lvlF * -2.0f * p.y;
        float bz = lvlF * -2.0f * p.z, bc = lvlF * p.w;
        bx2[r] = pk(bx, bx); by2[r] = pk(by, by);
        bz2[r] = pk(bz, bz); bc2[r] = pk(bc, bc);
        rsPrev[r] = g_rowscale[b][n];
        liveA[r] = (!LAST) && (lvl2c * g_rowmin[b][n] >= SKIP_X);
        anyA |= liveA[r];
        anyC |= (rsPrev[r] != 0.0f);
    }
    if (LAST && threadIdx.x == 0) {
        float s = 0.0f;
        #pragma unroll
        for (int mt = 0; mt < NMT; mt++) s += g_sumRPart[b][mt];
        s_sumR = s;
    }
    int ctaAny = __syncthreads_or((anyA || anyC) ? 1 : 0);

    ull accA[RPW] = {0ull, 0ull}, accC[RPW] = {0ull, 0ull};
    if (ctaAny) {
        for (int j = threadIdx.x; j < kM / 2; j += 256) {
            float4 qa = g_P2[b][2 * j], qb = g_P2[b][2 * j + 1];
            s_xy[j] = make_float4(qa.x, qb.x, qa.y, qb.y);
            s_zc[j] = make_float4(qa.z, qb.z, lvlF * qa.w, lvlF * qb.w);
            s_w [j] = g_wpk[b][j];                      // packed (rf0,rf1,rr0,rr1)
        }
        __syncthreads();
        #pragma unroll 2
        for (int j = lane; j < kM / 2; j += 32) {
            ulonglong2 xy = *reinterpret_cast<const ulonglong2*>(&s_xy[j]);
            ulonglong2 zc = *reinterpret_cast<const ulonglong2*>(&s_zc[j]);
            ulonglong2 w  = *reinterpret_cast<const ulonglong2*>(&s_w [j]);
            #pragma unroll
            for (int r = 0; r < RPW; r++) {
                ull a = add2(bc2[r], zc.y);
                a = fma2(bx2[r], xy.x, a);
                a = fma2(by2[r], xy.y, a);
                a = fma2(bz2[r], zc.x, a);
                float2 af = upk(a);
                ull e = pk(ex2f(af.x), ex2f(af.y));
                if (!LAST) {
                    ull e2 = mul2(e, e);
                    ull e4 = mul2(e2, e2);
                    accC[r] = fma2(e4, w.x, accC[r]);
                    accA[r] = fma2(e, w.y, accA[r]);
                } else {
                    accC[r] = fma2(e, w.x, accC[r]);
                }
            }
        }
    }

    #pragma unroll
    for (int r = 0; r < RPW; r++) {
        float2 c2 = upk(accC[r]);
        float2 a2 = upk(accA[r]);
        float sC = warp_sum(c2.x + c2.y);
        float sA = warp_sum(a2.x + a2.y);
        if (lane == 0) {
            int n = rowbase + warp * RPW + r;
            float remL = g_remainL[b][n];
            remL = fmaxf(remL - rsPrev[r] * sC, 0.0f);
            g_remainL[b][n] = remL;
            float rs;
            if (LAST)            rs = remL / (s_sumR + 1e-9f);
            else if (liveA[r])   rs = remL / (sA + 1e-9f);
            else                 rs = 0.0f;
            g_rowscale[b][n] = rs;
            float lg = (rs > 0.0f) ? lg2f(rs) : DEAD_LG;
            float l2 = LAST ? 0.0f : lvl2c;
            float4 p = g_P1[b][n];
            g_rowB[b][n] = make_float4(l2 * -2.0f * p.x, l2 * -2.0f * p.y,
                                       l2 * -2.0f * p.z, fmaf(l2, p.w, lg));
        }
    }
}

// ---------------- fused pass B + E ----------------
// Column partials with rowscale folded as lg2, d from fp16 table; the last CTA per
// (b, mtile) group (ticket election, deterministic fixed-order sums) runs the E
// phase: clip, cost, remainR update, packed weight write for next AC.
__global__ void __launch_bounds__(256) k_passBE(float lvl2) {
    __shared__ float4 sXY[NCHUNK / 2];   // (x0,x1,y0,y1) of rowB, row-pair packed
    __shared__ float4 sZC[NCHUNK / 2];   // (z0,z1,c0,c1)
    __shared__ float  r1[256], r2[256];
    __shared__ float  sRf[256], sNr[256];
    __shared__ unsigned int s_arr;
    int cta = blockIdx.x;
    int b = cta / (NMT * NCHUNKS);
    int rem = cta % (NMT * NCHUNKS);
    int mtile = rem / NCHUNKS;
    int chunk = rem % NCHUNKS;
    int nbase = chunk * NCHUNK;

    bool liveT = false;
    if (threadIdx.x < NCHUNK / 2) {
        float4 r0 = g_rowB[b][nbase + 2 * threadIdx.x];
        float4 rr = g_rowB[b][nbase + 2 * threadIdx.x + 1];
        sXY[threadIdx.x] = make_float4(r0.x, rr.x, r0.y, rr.y);
        sZC[threadIdx.x] = make_float4(r0.z, rr.z, r0.w, rr.w);
        liveT = (r0.w > -1e29f) || (rr.w > -1e29f);
    }
    int any = __syncthreads_or(liveT ? 1 : 0);
    int m = mtile * MTILE + threadIdx.x;

    if (any) {
        float4 q = g_P2[b][m];
        float qc = lvl2 * q.w;
        ull qxx = pk(q.x, q.x), qyy = pk(q.y, q.y), qzz = pk(q.z, q.z), qcc = pk(qc, qc);
        const __half2* dp = &g_d16[b][nbase >> 1][m];
        ull csA = 0ull, cdA = 0ull, csB = 0ull, cdB = 0ull;   // dual chains (even/odd j)
        #pragma unroll 4
        for (int j = 0; j < NCHUNK / 2; j += 2) {
            {
                ulonglong2 xy = *reinterpret_cast<const ulonglong2*>(&sXY[j]);
                ulonglong2 zc = *reinterpret_cast<const ulonglong2*>(&sZC[j]);
                ull a = add2(zc.y, qcc);
                a = fma2(xy.x, qxx, a);
                a = fma2(xy.y, qyy, a);
                a = fma2(zc.x, qzz, a);
                float2 af = upk(a);
                ull e = pk(ex2f(af.x), ex2f(af.y));
                csA = add2(csA, e);
                float2 df = __half22float2(dp[j * kM]);
                cdA = fma2(e, pk(df.x, df.y), cdA);
            }
            {
                ulonglong2 xy = *reinterpret_cast<const ulonglong2*>(&sXY[j + 1]);
                ulonglong2 zc = *reinterpret_cast<const ulonglong2*>(&sZC[j + 1]);
                ull a = add2(zc.y, qcc);
                a = fma2(xy.x, qxx, a);
                a = fma2(xy.y, qyy, a);
                a = fma2(zc.x, qzz, a);
                float2 af = upk(a);
                ull e = pk(ex2f(af.x), ex2f(af.y));
                csB = add2(csB, e);
                float2 df = __half22float2(dp[(j + 1) * kM]);
                cdB = fma2(e, pk(df.x, df.y), cdB);
            }
        }
        float2 ca = upk(csA), cb = upk(csB), da = upk(cdA), db = upk(cdB);
        float remR = g_remainR[b][m];
        g_colsum[b][chunk][m]  = ((ca.x + ca.y) + (cb.x + cb.y)) * remR;
        g_colsumd[b][chunk][m] = ((da.x + da.y) + (db.x + db.y)) * remR;
    } else {
        g_colsum[b][chunk][m]  = 0.0f;
        g_colsumd[b][chunk][m] = 0.0f;
    }

    // -- arrive: elect the last CTA of this (b, mtile) group to run the E phase --
    __threadfence();
    __syncthreads();
    if (threadIdx.x == 0) s_arr = atomicAdd(&g_ticket[b][mtile], 1u);
    __syncthreads();
    if (s_arr != NCHUNKS - 1) return;
    __threadfence();                               // see all groups' partial writes

    float cs = 0.0f, csd = 0.0f;
    #pragma unroll
    for (int c = 0; c < NCHUNKS; c++) { cs += g_colsum[b][c][m]; csd += g_colsumd[b][c][m]; }
    float rr = g_remainR[b][m];
    float csc = fminf(rr / (cs + 1e-9f), 1.0f);
    float rf = rr * csc;
    float nr = fmaxf(rr - cs * csc, 0.0f);
    g_remainR[b][m] = nr;
    sRf[threadIdx.x] = rf;
    sNr[threadIdx.x] = nr;
    r1[threadIdx.x] = csd * csc;
    r2[threadIdx.x] = nr;
    __syncthreads();
    if (threadIdx.x < MTILE / 2) {                 // packed weights for next AC launch
        int t = threadIdx.x;
        g_wpk[b][mtile * (MTILE / 2) + t] =
            make_float4(sRf[2 * t], sRf[2 * t + 1], sNr[2 * t], sNr[2 * t + 1]);
    }
    #pragma unroll
    for (int s = 128; s > 0; s >>= 1) {
        if (threadIdx.x < s) {
            r1[threadIdx.x] += r1[threadIdx.x + s];
            r2[threadIdx.x] += r2[threadIdx.x + s];
        }
        __syncthreads();
    }
    if (threadIdx.x == 0) {
        g_costPart[b][mtile] += r1[0];
        g_sumRPart[b][mtile] = r2[0];
        g_ticket[b][mtile] = 0u;                   // re-arm for next level / next replay
    }
}

// ---------------- final: reduce cost partials into out ----------------
__global__ void k_final(float* __restrict__ out) {
    int b = blockIdx.x;
    int lane = threadIdx.x;
    float v = (lane < NMT) ? g_costPart[b][lane] : 0.0f;
    v = warp_sum(v);
    if (lane == 0) out[b] = v;
}

// ---------------- launch ----------------
extern "C" void kernel_launch(void* const* d_in, const int* in_sizes, int n_in,
                              void* d_out, int out_size) {
    const float* in1 = (const float*)d_in[0];
    const float* in2 = (const float*)d_in[1];
    float* out = (float*)d_out;

    static const float levels[10] = {
        -16384.f, -4096.f, -1024.f, -256.f, -64.f, -16.f, -4.f, -1.f, -0.25f, 0.f
    };

    k_init<<<(kB * kN + 255) / 256, 256>>>(in1, in2);
    k_rowmin<<<kB * (kN / 32), 256>>>();
    k_dprep<<<GRID_B, 256>>>();
    float lp = 0.0f;
    for (int j = 0; j < 10; j++) {
        float lc = levels[j] * LOG2E;
        if (j < 9) k_fusedAC<false><<<GRID_AC, 256>>>(lp, lc);
        else       k_fusedAC<true ><<<GRID_AC, 256>>>(lp, lc);
        k_passBE<<<GRID_B, 256>>>(lc);
        lp = lc;
    }
    k_final<<<kB, 32>>>(out);
}